// round 1
// baseline (speedup 1.0000x reference)
#include <cuda_runtime.h>
#include <cstdint>

// Problem constants
#define BATCH   4
#define SEQ     2048
#define DIM     1024          // input dim D
#define HEADS   16
#define DH      64            // key size == size per head
#define MTOT    (BATCH*SEQ)   // 8192 rows
#define NEG_BIG 1e10f

// ---------------------------------------------------------------------------
// Scratch: projected Q/K/V, [B*S, H*DH] row-major. 3 x 32 MB device globals.
// ---------------------------------------------------------------------------
__device__ float g_qw[(size_t)MTOT * DIM];
__device__ float g_kw[(size_t)MTOT * DIM];
__device__ float g_vw[(size_t)MTOT * DIM];

// ---------------------------------------------------------------------------
// SGEMM: C[MTOT,1024] = A[MTOT,1024] @ W[1024,1024]   (all row-major, fp32)
// BM=BN=128, BK=16, TM=TN=8, 256 threads.
// ---------------------------------------------------------------------------
#define BM 128
#define BN 128
#define BKG 16
#define TM 8
#define TN 8

__global__ __launch_bounds__(256) void sgemm_kernel(
    const float* __restrict__ A,
    const float* __restrict__ W,
    float* __restrict__ C)
{
    __shared__ float As[BKG][BM + 4];   // stored transposed: As[k][m]
    __shared__ float Bs[BKG][BN + 4];

    const int bx = blockIdx.x;              // N tile
    const int by = blockIdx.y;              // M tile
    const int tid = threadIdx.x;
    const int tx = tid & 15;                // 0..15
    const int ty = tid >> 4;                // 0..15
    const int row0 = by * BM;
    const int col0 = bx * BN;

    float acc[TM][TN];
    #pragma unroll
    for (int i = 0; i < TM; i++)
        #pragma unroll
        for (int j = 0; j < TN; j++) acc[i][j] = 0.f;

    for (int kt = 0; kt < DIM; kt += BKG) {
        // Load A tile (128x16) transposed into As
        #pragma unroll
        for (int p = 0; p < 2; p++) {
            int idx = tid + p * 256;            // 0..511 float4s
            int r  = idx >> 2;                  // 0..127
            int c4 = idx & 3;                   // 0..3
            float4 v = *(const float4*)&A[(size_t)(row0 + r) * DIM + kt + c4 * 4];
            As[c4 * 4 + 0][r] = v.x;
            As[c4 * 4 + 1][r] = v.y;
            As[c4 * 4 + 2][r] = v.z;
            As[c4 * 4 + 3][r] = v.w;
        }
        // Load B tile (16x128)
        #pragma unroll
        for (int p = 0; p < 2; p++) {
            int idx = tid + p * 256;            // 0..511 float4s
            int r  = idx >> 5;                  // 0..15
            int c4 = idx & 31;                  // 0..31
            *(float4*)&Bs[r][c4 * 4] =
                *(const float4*)&W[(size_t)(kt + r) * DIM + col0 + c4 * 4];
        }
        __syncthreads();

        #pragma unroll
        for (int k = 0; k < BKG; k++) {
            float4 a0 = *(const float4*)&As[k][ty * TM];
            float4 a1 = *(const float4*)&As[k][ty * TM + 4];
            float4 b0 = *(const float4*)&Bs[k][tx * TN];
            float4 b1 = *(const float4*)&Bs[k][tx * TN + 4];
            float fa[TM] = {a0.x,a0.y,a0.z,a0.w,a1.x,a1.y,a1.z,a1.w};
            float fb[TN] = {b0.x,b0.y,b0.z,b0.w,b1.x,b1.y,b1.z,b1.w};
            #pragma unroll
            for (int i = 0; i < TM; i++)
                #pragma unroll
                for (int j = 0; j < TN; j++)
                    acc[i][j] += fa[i] * fb[j];
        }
        __syncthreads();
    }

    #pragma unroll
    for (int i = 0; i < TM; i++) {
        int r = row0 + ty * TM + i;
        #pragma unroll
        for (int j = 0; j < TN; j += 4) {
            float4 v = make_float4(acc[i][j], acc[i][j+1], acc[i][j+2], acc[i][j+3]);
            *(float4*)&C[(size_t)r * DIM + col0 + tx * TN + j] = v;
        }
    }
}

// ---------------------------------------------------------------------------
// Flash attention: per (b,h,q-tile of 64). BKV=64. 256 threads: 16x16 grid,
// each thread owns 4 rows x 4 cols. Online softmax; O accumulated in regs.
//
// Smem layouts (floats):
//   Qs[r][k]  stride 65  (scalar reads, broadcast-friendly)
//   Ks[k][c]  stride 68  (float4 reads along c, 16B-aligned rows)
//   Vs[c][d]  stride 68  (float4 reads along d)
//   Ps[r][c]  stride 65  (scalar reads, broadcast-friendly)
//   maskS[64]
// ---------------------------------------------------------------------------
#define BQ  64
#define BKV 64
#define QS_OFF 0
#define QS_STR 65
#define KS_OFF (QS_OFF + 64*65)          // 4160, 16B-aligned (x4 bytes)
#define KS_STR 68
#define VS_OFF (KS_OFF + 64*68)          // 8512, 16B-aligned
#define VS_STR 68
#define PS_OFF (VS_OFF + 64*68)          // 12864
#define PS_STR 65
#define MK_OFF (PS_OFF + 64*65)          // 17024
#define SMEM_FLOATS (MK_OFF + 64)        // 17088 floats = 68352 bytes

__global__ __launch_bounds__(256) void flash_attn_kernel(
    const float* __restrict__ qw,
    const float* __restrict__ kw,
    const float* __restrict__ vw,
    const float* __restrict__ v_mask,
    const float* __restrict__ q_mask,
    float* __restrict__ out)
{
    extern __shared__ float smem[];
    float* Qs = smem + QS_OFF;
    float* Ks = smem + KS_OFF;
    float* Vs = smem + VS_OFF;
    float* Ps = smem + PS_OFF;
    float* maskS = smem + MK_OFF;

    const int tid = threadIdx.x;
    const int tx = tid & 15;             // col group (4 cols / dims)
    const int ty = tid >> 4;             // row group (4 rows)
    const int qtile = blockIdx.x;        // 0..31
    const int bh = blockIdx.y;           // 0..63
    const int b = bh / HEADS;
    const int h = bh % HEADS;
    const int q0 = qtile * BQ;

    const float* qbase = qw + (size_t)(b * SEQ + q0) * DIM + h * DH;

    // Load Q tile (scaled by 1/sqrt(dh) at load)
    #pragma unroll
    for (int p = 0; p < 4; p++) {
        int e4 = tid + p * 256;          // 0..1023 float4s
        int r  = e4 >> 4;                // 0..63
        int k4 = e4 & 15;                // 0..15
        float4 v = *(const float4*)&qbase[(size_t)r * DIM + k4 * 4];
        Qs[r * QS_STR + k4 * 4 + 0] = v.x * 0.125f;
        Qs[r * QS_STR + k4 * 4 + 1] = v.y * 0.125f;
        Qs[r * QS_STR + k4 * 4 + 2] = v.z * 0.125f;
        Qs[r * QS_STR + k4 * 4 + 3] = v.w * 0.125f;
    }

    float m_i[4], l_i[4], o[4][4];
    #pragma unroll
    for (int i = 0; i < 4; i++) {
        m_i[i] = -1e30f; l_i[i] = 0.f;
        #pragma unroll
        for (int j = 0; j < 4; j++) o[i][j] = 0.f;
    }

    for (int kt = 0; kt < SEQ / BKV; kt++) {
        const int c0 = kt * BKV;
        const float* kbase = kw + (size_t)(b * SEQ + c0) * DIM + h * DH;
        const float* vbase = vw + (size_t)(b * SEQ + c0) * DIM + h * DH;

        __syncthreads();   // previous iteration's PV / P-writes done

        // Load K tile transposed: Ks[k][c]
        #pragma unroll
        for (int p = 0; p < 4; p++) {
            int e4 = tid + p * 256;
            int c  = e4 >> 4;            // KV row (col of S)
            int k4 = e4 & 15;
            float4 v = *(const float4*)&kbase[(size_t)c * DIM + k4 * 4];
            Ks[(k4 * 4 + 0) * KS_STR + c] = v.x;
            Ks[(k4 * 4 + 1) * KS_STR + c] = v.y;
            Ks[(k4 * 4 + 2) * KS_STR + c] = v.z;
            Ks[(k4 * 4 + 3) * KS_STR + c] = v.w;
        }
        // Load V tile: Vs[c][d]
        #pragma unroll
        for (int p = 0; p < 4; p++) {
            int e4 = tid + p * 256;
            int c  = e4 >> 4;
            int d4 = e4 & 15;
            float4 v = *(const float4*)&vbase[(size_t)c * DIM + d4 * 4];
            *(float4*)&Vs[c * VS_STR + d4 * 4] = v;
        }
        if (tid < BKV) maskS[tid] = v_mask[b * SEQ + c0 + tid];
        __syncthreads();

        // S = Q K^T (Q pre-scaled)
        float sacc[4][4];
        #pragma unroll
        for (int i = 0; i < 4; i++)
            #pragma unroll
            for (int j = 0; j < 4; j++) sacc[i][j] = 0.f;

        #pragma unroll 8
        for (int k = 0; k < DH; k++) {
            float qv0 = Qs[(ty * 4 + 0) * QS_STR + k];
            float qv1 = Qs[(ty * 4 + 1) * QS_STR + k];
            float qv2 = Qs[(ty * 4 + 2) * QS_STR + k];
            float qv3 = Qs[(ty * 4 + 3) * QS_STR + k];
            float4 kv = *(const float4*)&Ks[k * KS_STR + tx * 4];
            sacc[0][0] += qv0 * kv.x; sacc[0][1] += qv0 * kv.y;
            sacc[0][2] += qv0 * kv.z; sacc[0][3] += qv0 * kv.w;
            sacc[1][0] += qv1 * kv.x; sacc[1][1] += qv1 * kv.y;
            sacc[1][2] += qv1 * kv.z; sacc[1][3] += qv1 * kv.w;
            sacc[2][0] += qv2 * kv.x; sacc[2][1] += qv2 * kv.y;
            sacc[2][2] += qv2 * kv.z; sacc[2][3] += qv2 * kv.w;
            sacc[3][0] += qv3 * kv.x; sacc[3][1] += qv3 * kv.y;
            sacc[3][2] += qv3 * kv.z; sacc[3][3] += qv3 * kv.w;
        }

        // Additive key mask
        float msub[4];
        #pragma unroll
        for (int j = 0; j < 4; j++)
            msub[j] = (1.0f - maskS[tx * 4 + j]) * NEG_BIG;
        #pragma unroll
        for (int i = 0; i < 4; i++)
            #pragma unroll
            for (int j = 0; j < 4; j++)
                sacc[i][j] -= msub[j];

        // Row max (reduce over 16 col-threads, all in same warp half)
        float rmax[4];
        #pragma unroll
        for (int i = 0; i < 4; i++) {
            float m = fmaxf(fmaxf(sacc[i][0], sacc[i][1]),
                            fmaxf(sacc[i][2], sacc[i][3]));
            #pragma unroll
            for (int off = 8; off >= 1; off >>= 1)
                m = fmaxf(m, __shfl_xor_sync(0xffffffffu, m, off));
            rmax[i] = m;
        }

        // Online softmax update
        #pragma unroll
        for (int i = 0; i < 4; i++) {
            float mn = fmaxf(m_i[i], rmax[i]);
            float fi = __expf(m_i[i] - mn);
            m_i[i] = mn;
            l_i[i] *= fi;
            #pragma unroll
            for (int j = 0; j < 4; j++) o[i][j] *= fi;
        }

        // P = exp(S - m), row sums, write P to smem
        #pragma unroll
        for (int i = 0; i < 4; i++) {
            float rs = 0.f;
            #pragma unroll
            for (int j = 0; j < 4; j++) {
                float p = __expf(sacc[i][j] - m_i[i]);
                Ps[(ty * 4 + i) * PS_STR + tx * 4 + j] = p;
                rs += p;
            }
            #pragma unroll
            for (int off = 8; off >= 1; off >>= 1)
                rs += __shfl_xor_sync(0xffffffffu, rs, off);
            l_i[i] += rs;
        }
        __syncthreads();

        // O += P @ V
        #pragma unroll 8
        for (int c = 0; c < BKV; c++) {
            float p0 = Ps[(ty * 4 + 0) * PS_STR + c];
            float p1 = Ps[(ty * 4 + 1) * PS_STR + c];
            float p2 = Ps[(ty * 4 + 2) * PS_STR + c];
            float p3 = Ps[(ty * 4 + 3) * PS_STR + c];
            float4 vv = *(const float4*)&Vs[c * VS_STR + tx * 4];
            o[0][0] += p0 * vv.x; o[0][1] += p0 * vv.y;
            o[0][2] += p0 * vv.z; o[0][3] += p0 * vv.w;
            o[1][0] += p1 * vv.x; o[1][1] += p1 * vv.y;
            o[1][2] += p1 * vv.z; o[1][3] += p1 * vv.w;
            o[2][0] += p2 * vv.x; o[2][1] += p2 * vv.y;
            o[2][2] += p2 * vv.z; o[2][3] += p2 * vv.w;
            o[3][0] += p3 * vv.x; o[3][1] += p3 * vv.y;
            o[3][2] += p3 * vv.z; o[3][3] += p3 * vv.w;
        }
    }

    // Epilogue: O / l * q_mask
    #pragma unroll
    for (int i = 0; i < 4; i++) {
        int r = q0 + ty * 4 + i;
        float inv = (l_i[i] > 0.f) ? (1.0f / l_i[i]) : 0.f;
        float qm = q_mask[b * SEQ + r] * inv;
        float4 v = make_float4(o[i][0] * qm, o[i][1] * qm,
                               o[i][2] * qm, o[i][3] * qm);
        *(float4*)&out[(size_t)(b * SEQ + r) * (HEADS * DH) + h * DH + tx * 4] = v;
    }
}

// ---------------------------------------------------------------------------
// Launch
// ---------------------------------------------------------------------------
extern "C" void kernel_launch(void* const* d_in, const int* in_sizes, int n_in,
                              void* d_out, int out_size)
{
    const float* q_value = (const float*)d_in[0];
    const float* k_value = (const float*)d_in[1];
    const float* v_value = (const float*)d_in[2];
    const float* v_mask  = (const float*)d_in[3];
    const float* q_mask  = (const float*)d_in[4];
    const float* Wq      = (const float*)d_in[5];
    const float* Wk      = (const float*)d_in[6];
    const float* Wv      = (const float*)d_in[7];
    float* out = (float*)d_out;

    float *qw, *kw, *vw;
    cudaGetSymbolAddress((void**)&qw, g_qw);
    cudaGetSymbolAddress((void**)&kw, g_kw);
    cudaGetSymbolAddress((void**)&vw, g_vw);

    dim3 gGrid(DIM / BN, MTOT / BM);   // (8, 64)
    sgemm_kernel<<<gGrid, 256>>>(q_value, Wq, qw);
    sgemm_kernel<<<gGrid, 256>>>(k_value, Wk, kw);
    sgemm_kernel<<<gGrid, 256>>>(v_value, Wv, vw);

    const int smem_bytes = SMEM_FLOATS * (int)sizeof(float);   // 68352
    cudaFuncSetAttribute(flash_attn_kernel,
                         cudaFuncAttributeMaxDynamicSharedMemorySize, smem_bytes);
    dim3 aGrid(SEQ / BQ, BATCH * HEADS);   // (32, 64)
    flash_attn_kernel<<<aGrid, 256, smem_bytes>>>(qw, kw, vw, v_mask, q_mask, out);
}

// round 2
// speedup vs baseline: 1.0336x; 1.0336x over previous
#include <cuda_runtime.h>
#include <cstdint>

typedef unsigned long long ull;

// Problem constants
#define BATCH   4
#define SEQ     2048
#define DIM     1024
#define HEADS   16
#define DH      64
#define MTOT    (BATCH*SEQ)   // 8192
#define NEG_BIG 1e10f

// ---------------------------------------------------------------------------
// f32x2 packed-math helpers (sm_103a FFMA2 path; ptxas never emits this from C++)
// ---------------------------------------------------------------------------
__device__ __forceinline__ void fma2(ull &d, ull a, ull b) {
    asm("fma.rn.f32x2 %0, %1, %2, %0;" : "+l"(d) : "l"(a), "l"(b));
}
__device__ __forceinline__ ull mul2(ull a, ull b) {
    ull r; asm("mul.rn.f32x2 %0, %1, %2;" : "=l"(r) : "l"(a), "l"(b)); return r;
}
__device__ __forceinline__ ull dup2(float x) {
    ull r; asm("mov.b64 %0, {%1, %1};" : "=l"(r) : "f"(x)); return r;
}
__device__ __forceinline__ ull pack2(float lo, float hi) {
    ull r; asm("mov.b64 %0, {%1, %2};" : "=l"(r) : "f"(lo), "f"(hi)); return r;
}
__device__ __forceinline__ float2 unpk(ull v) {
    float2 r; asm("mov.b64 {%0, %1}, %2;" : "=f"(r.x), "=f"(r.y) : "l"(v)); return r;
}

// ---------------------------------------------------------------------------
// Scratch: projected Q/K/V, [B*S, H*DH] row-major.
// ---------------------------------------------------------------------------
__device__ float g_qw[(size_t)MTOT * DIM];
__device__ float g_kw[(size_t)MTOT * DIM];
__device__ float g_vw[(size_t)MTOT * DIM];

// ---------------------------------------------------------------------------
// SGEMM: C[MTOT,1024] = A[MTOT,1024] @ W[1024,1024], fp32, f32x2 inner loop.
// BM=BN=128, BK=16, 256 threads, 8x8 per thread (cols packed in pairs).
// A stored DUPLICATED in smem so the broadcast operand loads as dup-pairs.
// ---------------------------------------------------------------------------
#define BM 128
#define BN 128
#define BKG 16

__global__ __launch_bounds__(256, 2) void sgemm_kernel(
    const float* __restrict__ A,
    const float* __restrict__ W,
    float* __restrict__ C)
{
    __shared__ float As2[BKG][264];   // duplicated: As2[k][2m]=As2[k][2m+1]=A[m][k]
    __shared__ float Bs[BKG][136];

    const int bx = blockIdx.x;
    const int by = blockIdx.y;
    const int tid = threadIdx.x;
    const int tx = tid & 15;
    const int ty = tid >> 4;
    const int row0 = by * BM;
    const int col0 = bx * BN;

    ull acc2[8][4];
    #pragma unroll
    for (int i = 0; i < 8; i++)
        #pragma unroll
        for (int j = 0; j < 4; j++) acc2[i][j] = 0ull;

    for (int kt = 0; kt < DIM; kt += BKG) {
        // Load A tile (128x16), store transposed + duplicated
        #pragma unroll
        for (int p = 0; p < 2; p++) {
            int idx = tid + p * 256;            // 0..511 float4s
            int r  = idx >> 2;                  // 0..127
            int c4 = idx & 3;                   // 0..3
            float4 v = *(const float4*)&A[(size_t)(row0 + r) * DIM + kt + c4 * 4];
            *(ull*)&As2[c4 * 4 + 0][2 * r] = dup2(v.x);
            *(ull*)&As2[c4 * 4 + 1][2 * r] = dup2(v.y);
            *(ull*)&As2[c4 * 4 + 2][2 * r] = dup2(v.z);
            *(ull*)&As2[c4 * 4 + 3][2 * r] = dup2(v.w);
        }
        // Load B tile (16x128)
        #pragma unroll
        for (int p = 0; p < 2; p++) {
            int idx = tid + p * 256;
            int r  = idx >> 5;                  // 0..15
            int c4 = idx & 31;                  // 0..31
            *(float4*)&Bs[r][c4 * 4] =
                *(const float4*)&W[(size_t)(kt + r) * DIM + col0 + c4 * 4];
        }
        __syncthreads();

        #pragma unroll
        for (int k = 0; k < BKG; k++) {
            const ull* ap = (const ull*)&As2[k][ty * 16];
            const ull* bp = (const ull*)&Bs[k][tx * 8];
            ull a[8], b[4];
            #pragma unroll
            for (int i = 0; i < 8; i++) a[i] = ap[i];
            #pragma unroll
            for (int j = 0; j < 4; j++) b[j] = bp[j];
            #pragma unroll
            for (int i = 0; i < 8; i++)
                #pragma unroll
                for (int j = 0; j < 4; j++)
                    fma2(acc2[i][j], a[i], b[j]);
        }
        __syncthreads();
    }

    #pragma unroll
    for (int i = 0; i < 8; i++) {
        ull* cp = (ull*)&C[(size_t)(row0 + ty * 8 + i) * DIM + col0 + tx * 8];
        #pragma unroll
        for (int j = 0; j < 4; j++) cp[j] = acc2[i][j];
    }
}

// ---------------------------------------------------------------------------
// Flash attention, f32x2. BQ=128, BKV=64. 256 threads (16x16): each thread
// owns 8 S-rows (4 packed pairs) x 4 S-cols, and 8 O-rows x 4 head-dims.
//
// Smem (floats):
//   Qt[d][q]  d=64 rows, q=128+pad   (Q transposed -> row pairs load packed)
//   Kt[d][c]  d=64, c=64+pad
//   Vs[c][d]  64 x 64+pad
//   Pt[c][q]  c=64, q=128+pad        (P transposed -> row pairs load packed)
// ---------------------------------------------------------------------------
#define BQ  128
#define BKV 64
#define QT_STR 140
#define KT_STR 76
#define VSA_STR 68
#define PT_STR 140
#define QT_OFF 0
#define KT_OFF (QT_OFF + 64*QT_STR)          // 8960
#define VSA_OFF (KT_OFF + 64*KT_STR)         // 13824
#define PT_OFF (VSA_OFF + 64*VSA_STR)        // 18176
#define MK_OFF (PT_OFF + 64*PT_STR)          // 27136
#define FA_SMEM_FLOATS (MK_OFF + 64)         // 27200 floats = 108800 B

__global__ __launch_bounds__(256, 2) void flash_attn_kernel(
    const float* __restrict__ qw,
    const float* __restrict__ kw,
    const float* __restrict__ vw,
    const float* __restrict__ v_mask,
    const float* __restrict__ q_mask,
    float* __restrict__ out)
{
    extern __shared__ float smem[];
    float* Qt = smem + QT_OFF;
    float* Kt = smem + KT_OFF;
    float* Vs = smem + VSA_OFF;
    float* Pt = smem + PT_OFF;
    float* maskS = smem + MK_OFF;

    const int tid = threadIdx.x;
    const int tx = tid & 15;
    const int ty = tid >> 4;
    const int qtile = blockIdx.x;
    const int bh = blockIdx.y;
    const int b = bh / HEADS;
    const int h = bh % HEADS;
    const int q0 = qtile * BQ;

    const float* qbase = qw + (size_t)(b * SEQ + q0) * DIM + h * DH;

    // Load Q tile transposed (scaled by 1/sqrt(dh))
    #pragma unroll
    for (int p = 0; p < 8; p++) {
        int e4 = tid + p * 256;          // 0..2047 float4s
        int r  = e4 >> 4;                // 0..127
        int d4 = e4 & 15;                // 0..15
        float4 v = *(const float4*)&qbase[(size_t)r * DIM + d4 * 4];
        Qt[(d4 * 4 + 0) * QT_STR + r] = v.x * 0.125f;
        Qt[(d4 * 4 + 1) * QT_STR + r] = v.y * 0.125f;
        Qt[(d4 * 4 + 2) * QT_STR + r] = v.z * 0.125f;
        Qt[(d4 * 4 + 3) * QT_STR + r] = v.w * 0.125f;
    }

    float m_i[8], l_i[8];
    ull o2[4][4];
    #pragma unroll
    for (int i = 0; i < 8; i++) { m_i[i] = -1e30f; l_i[i] = 0.f; }
    #pragma unroll
    for (int i = 0; i < 4; i++)
        #pragma unroll
        for (int j = 0; j < 4; j++) o2[i][j] = 0ull;

    for (int kt = 0; kt < SEQ / BKV; kt++) {
        const int c0 = kt * BKV;
        const float* kbase = kw + (size_t)(b * SEQ + c0) * DIM + h * DH;
        const float* vbase = vw + (size_t)(b * SEQ + c0) * DIM + h * DH;

        __syncthreads();   // previous PV done reading Vs/Pt

        // K tile transposed: Kt[d][c];  V tile direct: Vs[c][d]
        #pragma unroll
        for (int p = 0; p < 4; p++) {
            int e4 = tid + p * 256;
            int c  = e4 >> 4;            // 0..63
            int d4 = e4 & 15;
            float4 v = *(const float4*)&kbase[(size_t)c * DIM + d4 * 4];
            Kt[(d4 * 4 + 0) * KT_STR + c] = v.x;
            Kt[(d4 * 4 + 1) * KT_STR + c] = v.y;
            Kt[(d4 * 4 + 2) * KT_STR + c] = v.z;
            Kt[(d4 * 4 + 3) * KT_STR + c] = v.w;
            float4 w = *(const float4*)&vbase[(size_t)c * DIM + d4 * 4];
            *(float4*)&Vs[c * VSA_STR + d4 * 4] = w;
        }
        if (tid < BKV) maskS[tid] = v_mask[b * SEQ + c0 + tid];
        __syncthreads();

        // S = Q K^T : rows packed in pairs (a), cols scalar-dup (b)
        ull s2[4][4];
        #pragma unroll
        for (int i = 0; i < 4; i++)
            #pragma unroll
            for (int j = 0; j < 4; j++) s2[i][j] = 0ull;

        #pragma unroll 4
        for (int d = 0; d < DH; d++) {
            const ull* qp = (const ull*)&Qt[d * QT_STR + ty * 8];
            float4 kv = *(const float4*)&Kt[d * KT_STR + tx * 4];
            ull a0 = qp[0], a1 = qp[1], a2 = qp[2], a3 = qp[3];
            ull b0 = dup2(kv.x), b1 = dup2(kv.y), b2 = dup2(kv.z), b3 = dup2(kv.w);
            fma2(s2[0][0], a0, b0); fma2(s2[0][1], a0, b1);
            fma2(s2[0][2], a0, b2); fma2(s2[0][3], a0, b3);
            fma2(s2[1][0], a1, b0); fma2(s2[1][1], a1, b1);
            fma2(s2[1][2], a1, b2); fma2(s2[1][3], a1, b3);
            fma2(s2[2][0], a2, b0); fma2(s2[2][1], a2, b1);
            fma2(s2[2][2], a2, b2); fma2(s2[2][3], a2, b3);
            fma2(s2[3][0], a3, b0); fma2(s2[3][1], a3, b1);
            fma2(s2[3][2], a3, b2); fma2(s2[3][3], a3, b3);
        }

        // Unpack S, apply additive key mask
        float s[8][4];
        #pragma unroll
        for (int ip = 0; ip < 4; ip++)
            #pragma unroll
            for (int j = 0; j < 4; j++) {
                float2 f = unpk(s2[ip][j]);
                s[2 * ip][j] = f.x;
                s[2 * ip + 1][j] = f.y;
            }
        float msub[4];
        #pragma unroll
        for (int j = 0; j < 4; j++)
            msub[j] = (1.0f - maskS[tx * 4 + j]) * NEG_BIG;
        #pragma unroll
        for (int i = 0; i < 8; i++)
            #pragma unroll
            for (int j = 0; j < 4; j++)
                s[i][j] -= msub[j];

        // Row max over 16 col-threads
        float fi[8];
        #pragma unroll
        for (int i = 0; i < 8; i++) {
            float m = fmaxf(fmaxf(s[i][0], s[i][1]), fmaxf(s[i][2], s[i][3]));
            #pragma unroll
            for (int off = 8; off >= 1; off >>= 1)
                m = fmaxf(m, __shfl_xor_sync(0xffffffffu, m, off));
            float mn = fmaxf(m_i[i], m);
            fi[i] = __expf(m_i[i] - mn);
            m_i[i] = mn;
            l_i[i] *= fi[i];
        }
        // Rescale O (packed pairs)
        #pragma unroll
        for (int ip = 0; ip < 4; ip++) {
            ull fp = pack2(fi[2 * ip], fi[2 * ip + 1]);
            #pragma unroll
            for (int j = 0; j < 4; j++) o2[ip][j] = mul2(o2[ip][j], fp);
        }

        // P = exp(S - m); transpose-write to Pt; row sums
        #pragma unroll
        for (int i = 0; i < 8; i++) {
            float rs = 0.f;
            #pragma unroll
            for (int j = 0; j < 4; j++) {
                s[i][j] = __expf(s[i][j] - m_i[i]);
                rs += s[i][j];
            }
            #pragma unroll
            for (int off = 8; off >= 1; off >>= 1)
                rs += __shfl_xor_sync(0xffffffffu, rs, off);
            l_i[i] += rs;
        }
        #pragma unroll
        for (int j = 0; j < 4; j++) {
            int c = tx * 4 + j;
            *(float4*)&Pt[c * PT_STR + ty * 8] =
                make_float4(s[0][j], s[1][j], s[2][j], s[3][j]);
            *(float4*)&Pt[c * PT_STR + ty * 8 + 4] =
                make_float4(s[4][j], s[5][j], s[6][j], s[7][j]);
        }
        __syncthreads();

        // O += P @ V : row pairs (a) from Pt, V scalar-dup (b)
        #pragma unroll 4
        for (int c = 0; c < BKV; c++) {
            const ull* pp = (const ull*)&Pt[c * PT_STR + ty * 8];
            float4 vv = *(const float4*)&Vs[c * VSA_STR + tx * 4];
            ull a0 = pp[0], a1 = pp[1], a2 = pp[2], a3 = pp[3];
            ull b0 = dup2(vv.x), b1 = dup2(vv.y), b2 = dup2(vv.z), b3 = dup2(vv.w);
            fma2(o2[0][0], a0, b0); fma2(o2[0][1], a0, b1);
            fma2(o2[0][2], a0, b2); fma2(o2[0][3], a0, b3);
            fma2(o2[1][0], a1, b0); fma2(o2[1][1], a1, b1);
            fma2(o2[1][2], a1, b2); fma2(o2[1][3], a1, b3);
            fma2(o2[2][0], a2, b0); fma2(o2[2][1], a2, b1);
            fma2(o2[2][2], a2, b2); fma2(o2[2][3], a2, b3);
            fma2(o2[3][0], a3, b0); fma2(o2[3][1], a3, b1);
            fma2(o2[3][2], a3, b2); fma2(o2[3][3], a3, b3);
        }
    }

    // Epilogue: O / l * q_mask
    #pragma unroll
    for (int ip = 0; ip < 4; ip++) {
        float2 c0 = unpk(o2[ip][0]);
        float2 c1 = unpk(o2[ip][1]);
        float2 c2 = unpk(o2[ip][2]);
        float2 c3 = unpk(o2[ip][3]);
        #pragma unroll
        for (int half = 0; half < 2; half++) {
            int i = 2 * ip + half;
            int r = q0 + ty * 8 + i;
            float inv = (l_i[i] > 0.f) ? (1.0f / l_i[i]) : 0.f;
            float qm = q_mask[b * SEQ + r] * inv;
            float4 v;
            if (half == 0)
                v = make_float4(c0.x * qm, c1.x * qm, c2.x * qm, c3.x * qm);
            else
                v = make_float4(c0.y * qm, c1.y * qm, c2.y * qm, c3.y * qm);
            *(float4*)&out[(size_t)(b * SEQ + r) * (HEADS * DH) + h * DH + tx * 4] = v;
        }
    }
}

// ---------------------------------------------------------------------------
// Launch
// ---------------------------------------------------------------------------
extern "C" void kernel_launch(void* const* d_in, const int* in_sizes, int n_in,
                              void* d_out, int out_size)
{
    const float* q_value = (const float*)d_in[0];
    const float* k_value = (const float*)d_in[1];
    const float* v_value = (const float*)d_in[2];
    const float* v_mask  = (const float*)d_in[3];
    const float* q_mask  = (const float*)d_in[4];
    const float* Wq      = (const float*)d_in[5];
    const float* Wk      = (const float*)d_in[6];
    const float* Wv      = (const float*)d_in[7];
    float* out = (float*)d_out;

    float *qw, *kw, *vw;
    cudaGetSymbolAddress((void**)&qw, g_qw);
    cudaGetSymbolAddress((void**)&kw, g_kw);
    cudaGetSymbolAddress((void**)&vw, g_vw);

    dim3 gGrid(DIM / BN, MTOT / BM);   // (8, 64)
    sgemm_kernel<<<gGrid, 256>>>(q_value, Wq, qw);
    sgemm_kernel<<<gGrid, 256>>>(k_value, Wk, kw);
    sgemm_kernel<<<gGrid, 256>>>(v_value, Wv, vw);

    const int smem_bytes = FA_SMEM_FLOATS * (int)sizeof(float);   // 108800
    cudaFuncSetAttribute(flash_attn_kernel,
                         cudaFuncAttributeMaxDynamicSharedMemorySize, smem_bytes);
    dim3 aGrid(SEQ / BQ, BATCH * HEADS);   // (16, 64)
    flash_attn_kernel<<<aGrid, 256, smem_bytes>>>(qw, kw, vw, v_mask, q_mask, out);
}

// round 7
// speedup vs baseline: 2.8108x; 2.7195x over previous
#include <cuda_runtime.h>
#include <cstdint>

typedef unsigned int u32;

#define BATCH   4
#define SEQ     2048
#define DIM     1024
#define HEADS   16
#define DH      64
#define MTOT    (BATCH*SEQ)
#define NEG_BIG 1e10f

// ---------------------------------------------------------------------------
// helpers
// ---------------------------------------------------------------------------
__device__ __forceinline__ float to_tf32(float x) {
    float r; asm("cvt.rna.tf32.f32 %0, %1;" : "=f"(r) : "f"(x)); return r;
}
__device__ __forceinline__ float4 cvt4(float4 v) {
    v.x = to_tf32(v.x); v.y = to_tf32(v.y); v.z = to_tf32(v.z); v.w = to_tf32(v.w);
    return v;
}
__device__ __forceinline__ u32 su32(const void* p) {
    return (u32)__cvta_generic_to_shared(p);
}
__device__ __forceinline__ void ldsm4(u32 &r0, u32 &r1, u32 &r2, u32 &r3, u32 addr) {
    asm volatile("ldmatrix.sync.aligned.m8n8.x4.shared.b16 {%0,%1,%2,%3}, [%4];"
        : "=r"(r0), "=r"(r1), "=r"(r2), "=r"(r3) : "r"(addr));
}
__device__ __forceinline__ void mma_tf32(float &c0, float &c1, float &c2, float &c3,
                                         u32 a0, u32 a1, u32 a2, u32 a3,
                                         u32 b0, u32 b1) {
    asm volatile("mma.sync.aligned.m16n8k8.row.col.f32.tf32.tf32.f32 "
                 "{%0,%1,%2,%3}, {%4,%5,%6,%7}, {%8,%9}, {%0,%1,%2,%3};"
        : "+f"(c0), "+f"(c1), "+f"(c2), "+f"(c3)
        : "r"(a0), "r"(a1), "r"(a2), "r"(a3), "r"(b0), "r"(b1));
}

// ---------------------------------------------------------------------------
// Scratch: projected Q/K/V (tf32-rounded fp32 bits), [B*S, 1024] row-major.
// ---------------------------------------------------------------------------
__device__ float g_qw[(size_t)MTOT * DIM];
__device__ float g_kw[(size_t)MTOT * DIM];
__device__ float g_vw[(size_t)MTOT * DIM];

// ---------------------------------------------------------------------------
// Projection GEMM: C[8192,1024] = tf32(A) @ tf32(W), fp32 accum.
// Block 128x128, BK=32, 256 thr = 8 warps in 4(m) x 2(n); warp tile 32x64.
// As[m][k] swizzled; Ws[n][k] (W transposed) swizzled.
// ---------------------------------------------------------------------------
__global__ __launch_bounds__(256) void proj_kernel(
    const float* __restrict__ A,
    const float* __restrict__ W,
    float* __restrict__ C)
{
    __shared__ float As[128 * 32];
    __shared__ float Ws[128 * 32];

    const int tid  = threadIdx.x;
    const int lane = tid & 31;
    const int warp = tid >> 5;
    const int wm = warp >> 1;            // 0..3
    const int wn = warp & 1;             // 0..1
    const int row0 = blockIdx.y * 128;
    const int col0 = blockIdx.x * 128;

    float acc[2][8][4];
    #pragma unroll
    for (int i = 0; i < 2; i++)
        #pragma unroll
        for (int j = 0; j < 8; j++)
            #pragma unroll
            for (int r = 0; r < 4; r++) acc[i][j][r] = 0.f;

    for (int kt = 0; kt < DIM; kt += 32) {
        // A tile: 128x32, float4 loads, swizzled STS.128
        #pragma unroll
        for (int p = 0; p < 4; p++) {
            int idx = tid + p * 256;
            int m  = idx >> 3;
            int c4 = idx & 7;
            float4 v = cvt4(*(const float4*)&A[(size_t)(row0 + m) * DIM + kt + 4 * c4]);
            int pc = c4 ^ (m & 7);
            *(float4*)&As[m * 32 + 4 * pc] = v;
        }
        // W tile: 32x128 -> Ws[n][k] transposed, scalar stores
        #pragma unroll
        for (int p = 0; p < 4; p++) {
            int idx = tid + p * 256;
            int k  = idx >> 5;
            int n4 = idx & 31;
            float4 v = cvt4(*(const float4*)&W[(size_t)(kt + k) * DIM + col0 + 4 * n4]);
            float vv[4] = {v.x, v.y, v.z, v.w};
            #pragma unroll
            for (int j = 0; j < 4; j++) {
                int n = 4 * n4 + j;
                int pc = (k >> 2) ^ (n & 7) ^ ((n >> 3) & 7);
                Ws[n * 32 + 4 * pc + (k & 3)] = vv[j];
            }
        }
        __syncthreads();

        #pragma unroll
        for (int ks = 0; ks < 4; ks++) {
            int chunk = 2 * ks + (lane >> 4);
            int rsel  = (lane & 7) + ((lane >> 3) & 1) * 8;
            // A fragments (2 m-frags)
            u32 a[2][4];
            #pragma unroll
            for (int mf = 0; mf < 2; mf++) {
                int row = wm * 32 + mf * 16 + rsel;
                int pc = chunk ^ (row & 7);
                ldsm4(a[mf][0], a[mf][1], a[mf][2], a[mf][3],
                      su32(&As[row * 32 + 4 * pc]));
            }
            // B fragments (8 n-frags via 4 x4-ldmatrix)
            u32 b[8][2];
            #pragma unroll
            for (int nfp = 0; nfp < 4; nfp++) {
                int row = wn * 64 + nfp * 16 + rsel;
                int pc = chunk ^ (row & 7) ^ ((row >> 3) & 7);
                u32 r0, r1, r2, r3;
                ldsm4(r0, r1, r2, r3, su32(&Ws[row * 32 + 4 * pc]));
                b[2 * nfp][0] = r0; b[2 * nfp][1] = r2;
                b[2 * nfp + 1][0] = r1; b[2 * nfp + 1][1] = r3;
            }
            #pragma unroll
            for (int mf = 0; mf < 2; mf++)
                #pragma unroll
                for (int nf = 0; nf < 8; nf++)
                    mma_tf32(acc[mf][nf][0], acc[mf][nf][1], acc[mf][nf][2], acc[mf][nf][3],
                             a[mf][0], a[mf][1], a[mf][2], a[mf][3],
                             b[nf][0], b[nf][1]);
        }
        __syncthreads();
    }

    // Epilogue: store tf32-rounded (consumed only by MMA downstream)
    const int g = lane >> 2;
    const int tg = lane & 3;
    #pragma unroll
    for (int mf = 0; mf < 2; mf++) {
        int r = row0 + wm * 32 + mf * 16 + g;
        #pragma unroll
        for (int nf = 0; nf < 8; nf++) {
            int c = col0 + wn * 64 + 8 * nf + 2 * tg;
            *(float2*)&C[(size_t)r * DIM + c] =
                make_float2(to_tf32(acc[mf][nf][0]), to_tf32(acc[mf][nf][1]));
            *(float2*)&C[(size_t)(r + 8) * DIM + c] =
                make_float2(to_tf32(acc[mf][nf][2]), to_tf32(acc[mf][nf][3]));
        }
    }
}

// ---------------------------------------------------------------------------
// Flash attention, tf32 mma. 128 threads = 4 warps; BQ=64 (16 q-rows/warp),
// BKV=64, DH=64. Q fragments register-resident; P reuses the Q smem region.
// smem: QP[64*64] | Ks[64*64] | Vt[64*64] | mask[64]
// ---------------------------------------------------------------------------
#define AQP_OFF 0
#define AKS_OFF (64*64)
#define AVT_OFF (2*64*64)
#define AMK_OFF (3*64*64)
#define A_SMEM_FLOATS (3*64*64 + 64)

__global__ __launch_bounds__(128) void attn_kernel(
    const float* __restrict__ qw,
    const float* __restrict__ kw,
    const float* __restrict__ vw,
    const float* __restrict__ v_mask,
    const float* __restrict__ q_mask,
    float* __restrict__ out)
{
    extern __shared__ float smem[];
    float* QP = smem + AQP_OFF;
    float* Ks = smem + AKS_OFF;
    float* Vt = smem + AVT_OFF;
    float* maskS = smem + AMK_OFF;

    const int tid  = threadIdx.x;
    const int lane = tid & 31;
    const int warp = tid >> 5;
    const int g  = lane >> 2;
    const int tg = lane & 3;
    const int q0 = blockIdx.x * 64;
    const int bh = blockIdx.y;
    const int b = bh / HEADS;
    const int h = bh % HEADS;

    const float* qbase = qw + (size_t)(b * SEQ + q0) * DIM + h * DH;

    // ---- Load Q tile (x 1/8, exact in tf32) into smem, swizzled ----
    #pragma unroll
    for (int p = 0; p < 8; p++) {
        int idx = tid + p * 128;
        int r  = idx >> 4;
        int c4 = idx & 15;
        float4 v = *(const float4*)&qbase[(size_t)r * DIM + 4 * c4];
        v.x *= 0.125f; v.y *= 0.125f; v.z *= 0.125f; v.w *= 0.125f;
        int pc = c4 ^ (r & 7);
        *(float4*)&QP[r * 64 + 4 * pc] = v;
    }
    __syncthreads();

    // ---- Q fragments: 8 k-steps, register resident ----
    const int rsel = (lane & 7) + ((lane >> 3) & 1) * 8;
    u32 qa[8][4];
    #pragma unroll
    for (int ks = 0; ks < 8; ks++) {
        int row = warp * 16 + rsel;
        int chunk = 2 * ks + (lane >> 4);
        int pc = chunk ^ (row & 7);
        ldsm4(qa[ks][0], qa[ks][1], qa[ks][2], qa[ks][3],
              su32(&QP[row * 64 + 4 * pc]));
    }
    __syncthreads();   // QP free for P reuse

    float o[8][4];
    float m_i[2] = {-1e30f, -1e30f};
    float l_i[2] = {0.f, 0.f};
    #pragma unroll
    for (int nf = 0; nf < 8; nf++)
        #pragma unroll
        for (int r = 0; r < 4; r++) o[nf][r] = 0.f;

    for (int kt = 0; kt < SEQ / 64; kt++) {
        const int c0 = kt * 64;
        const float* kbase = kw + (size_t)(b * SEQ + c0) * DIM + h * DH;
        const float* vbase = vw + (size_t)(b * SEQ + c0) * DIM + h * DH;

        __syncthreads();   // prev iteration consumers done

        // K tile natural [c][d], swizzled
        #pragma unroll
        for (int p = 0; p < 8; p++) {
            int idx = tid + p * 128;
            int r  = idx >> 4;
            int c4 = idx & 15;
            float4 v = *(const float4*)&kbase[(size_t)r * DIM + 4 * c4];
            int pc = c4 ^ (r & 7);
            *(float4*)&Ks[r * 64 + 4 * pc] = v;
        }
        // V tile transposed -> Vt[d][c], swizzled
        #pragma unroll
        for (int p = 0; p < 8; p++) {
            int idx = tid + p * 128;
            int c  = idx >> 4;
            int d4 = idx & 15;
            float4 v = *(const float4*)&vbase[(size_t)c * DIM + 4 * d4];
            float vv[4] = {v.x, v.y, v.z, v.w};
            #pragma unroll
            for (int j = 0; j < 4; j++) {
                int row = 4 * d4 + j;
                int pc = (c >> 2) ^ (row & 7) ^ ((row >> 3) & 7);
                Vt[row * 64 + 4 * pc + (c & 3)] = vv[j];
            }
        }
        if (tid < 64) maskS[tid] = v_mask[b * SEQ + c0 + tid];
        __syncthreads();

        // ---- S = Q K^T ----
        float s[8][4];
        #pragma unroll
        for (int nf = 0; nf < 8; nf++)
            #pragma unroll
            for (int r = 0; r < 4; r++) s[nf][r] = 0.f;

        #pragma unroll
        for (int ks = 0; ks < 8; ks++) {
            int chunk = 2 * ks + (lane >> 4);
            u32 kb[8][2];
            #pragma unroll
            for (int nfp = 0; nfp < 4; nfp++) {
                int row = nfp * 16 + rsel;
                int pc = chunk ^ (row & 7);
                u32 r0, r1, r2, r3;
                ldsm4(r0, r1, r2, r3, su32(&Ks[row * 64 + 4 * pc]));
                kb[2 * nfp][0] = r0; kb[2 * nfp][1] = r2;
                kb[2 * nfp + 1][0] = r1; kb[2 * nfp + 1][1] = r3;
            }
            #pragma unroll
            for (int nf = 0; nf < 8; nf++)
                mma_tf32(s[nf][0], s[nf][1], s[nf][2], s[nf][3],
                         qa[ks][0], qa[ks][1], qa[ks][2], qa[ks][3],
                         kb[nf][0], kb[nf][1]);
        }

        // ---- additive key mask ----
        #pragma unroll
        for (int nf = 0; nf < 8; nf++) {
            int col = 8 * nf + 2 * tg;
            float m0 = (1.0f - maskS[col])     * NEG_BIG;
            float m1 = (1.0f - maskS[col + 1]) * NEG_BIG;
            s[nf][0] -= m0; s[nf][1] -= m1;
            s[nf][2] -= m0; s[nf][3] -= m1;
        }

        // ---- online softmax ----
        float rmax0 = -1e30f, rmax1 = -1e30f;
        #pragma unroll
        for (int nf = 0; nf < 8; nf++) {
            rmax0 = fmaxf(rmax0, fmaxf(s[nf][0], s[nf][1]));
            rmax1 = fmaxf(rmax1, fmaxf(s[nf][2], s[nf][3]));
        }
        #pragma unroll
        for (int off = 1; off <= 2; off <<= 1) {
            rmax0 = fmaxf(rmax0, __shfl_xor_sync(0xffffffffu, rmax0, off));
            rmax1 = fmaxf(rmax1, __shfl_xor_sync(0xffffffffu, rmax1, off));
        }
        float mn0 = fmaxf(m_i[0], rmax0);
        float mn1 = fmaxf(m_i[1], rmax1);
        float fi0 = __expf(m_i[0] - mn0);
        float fi1 = __expf(m_i[1] - mn1);
        m_i[0] = mn0; m_i[1] = mn1;
        l_i[0] *= fi0; l_i[1] *= fi1;
        #pragma unroll
        for (int nf = 0; nf < 8; nf++) {
            o[nf][0] *= fi0; o[nf][1] *= fi0;
            o[nf][2] *= fi1; o[nf][3] *= fi1;
        }

        float ls0 = 0.f, ls1 = 0.f;
        #pragma unroll
        for (int nf = 0; nf < 8; nf++) {
            s[nf][0] = __expf(s[nf][0] - mn0);
            s[nf][1] = __expf(s[nf][1] - mn0);
            s[nf][2] = __expf(s[nf][2] - mn1);
            s[nf][3] = __expf(s[nf][3] - mn1);
            ls0 += s[nf][0] + s[nf][1];
            ls1 += s[nf][2] + s[nf][3];
        }
        #pragma unroll
        for (int off = 1; off <= 2; off <<= 1) {
            ls0 += __shfl_xor_sync(0xffffffffu, ls0, off);
            ls1 += __shfl_xor_sync(0xffffffffu, ls1, off);
        }
        l_i[0] += ls0; l_i[1] += ls1;

        // ---- P -> smem (tf32-rounded), per-warp private rows ----
        #pragma unroll
        for (int nf = 0; nf < 8; nf++) {
            int col = 8 * nf + 2 * tg;
            int chunk = col >> 2;
            int row = warp * 16 + g;
            int pc0 = chunk ^ (row & 7);
            *(float2*)&QP[row * 64 + 4 * pc0 + (col & 3)] =
                make_float2(to_tf32(s[nf][0]), to_tf32(s[nf][1]));
            int row2 = row + 8;
            int pc2 = chunk ^ (row2 & 7);
            *(float2*)&QP[row2 * 64 + 4 * pc2 + (col & 3)] =
                make_float2(to_tf32(s[nf][2]), to_tf32(s[nf][3]));
        }
        __syncwarp();

        // ---- O += P @ V ----
        #pragma unroll
        for (int ks = 0; ks < 8; ks++) {
            int chunk = 2 * ks + (lane >> 4);
            int prow = warp * 16 + rsel;
            int ppc = chunk ^ (prow & 7);
            u32 pa0, pa1, pa2, pa3;
            ldsm4(pa0, pa1, pa2, pa3, su32(&QP[prow * 64 + 4 * ppc]));

            u32 vb[8][2];
            #pragma unroll
            for (int nfp = 0; nfp < 4; nfp++) {
                int row = nfp * 16 + rsel;
                int pc = chunk ^ (row & 7) ^ ((row >> 3) & 7);
                u32 r0, r1, r2, r3;
                ldsm4(r0, r1, r2, r3, su32(&Vt[row * 64 + 4 * pc]));
                vb[2 * nfp][0] = r0; vb[2 * nfp][1] = r2;
                vb[2 * nfp + 1][0] = r1; vb[2 * nfp + 1][1] = r3;
            }
            #pragma unroll
            for (int nf = 0; nf < 8; nf++)
                mma_tf32(o[nf][0], o[nf][1], o[nf][2], o[nf][3],
                         pa0, pa1, pa2, pa3, vb[nf][0], vb[nf][1]);
        }
    }

    // ---- epilogue ----
    int r0g = q0 + warp * 16 + g;
    int r1g = r0g + 8;
    float inv0 = (l_i[0] > 0.f) ? 1.0f / l_i[0] : 0.f;
    float inv1 = (l_i[1] > 0.f) ? 1.0f / l_i[1] : 0.f;
    float qm0 = q_mask[b * SEQ + r0g] * inv0;
    float qm1 = q_mask[b * SEQ + r1g] * inv1;
    #pragma unroll
    for (int nf = 0; nf < 8; nf++) {
        int c = h * DH + 8 * nf + 2 * tg;
        *(float2*)&out[(size_t)(b * SEQ + r0g) * DIM + c] =
            make_float2(o[nf][0] * qm0, o[nf][1] * qm0);
        *(float2*)&out[(size_t)(b * SEQ + r1g) * DIM + c] =
            make_float2(o[nf][2] * qm1, o[nf][3] * qm1);
    }
}

// ---------------------------------------------------------------------------
// Launch
// ---------------------------------------------------------------------------
extern "C" void kernel_launch(void* const* d_in, const int* in_sizes, int n_in,
                              void* d_out, int out_size)
{
    const float* q_value = (const float*)d_in[0];
    const float* k_value = (const float*)d_in[1];
    const float* v_value = (const float*)d_in[2];
    const float* v_mask  = (const float*)d_in[3];
    const float* q_mask  = (const float*)d_in[4];
    const float* Wq      = (const float*)d_in[5];
    const float* Wk      = (const float*)d_in[6];
    const float* Wv      = (const float*)d_in[7];
    float* out = (float*)d_out;

    float *qw, *kw, *vw;
    cudaGetSymbolAddress((void**)&qw, g_qw);
    cudaGetSymbolAddress((void**)&kw, g_kw);
    cudaGetSymbolAddress((void**)&vw, g_vw);

    dim3 pGrid(DIM / 128, MTOT / 128);   // (8, 64)
    proj_kernel<<<pGrid, 256>>>(q_value, Wq, qw);
    proj_kernel<<<pGrid, 256>>>(k_value, Wk, kw);
    proj_kernel<<<pGrid, 256>>>(v_value, Wv, vw);

    const int smem_bytes = A_SMEM_FLOATS * (int)sizeof(float);   // 49408
    cudaFuncSetAttribute(attn_kernel,
                         cudaFuncAttributeMaxDynamicSharedMemorySize, smem_bytes);
    dim3 aGrid(SEQ / 64, BATCH * HEADS);   // (32, 64)
    attn_kernel<<<aGrid, 128, smem_bytes>>>(qw, kw, vw, v_mask, q_mask, out);
}

// round 8
// speedup vs baseline: 2.8214x; 1.0038x over previous
#include <cuda_runtime.h>
#include <cstdint>

typedef unsigned int u32;

#define BATCH   4
#define SEQ     2048
#define DIM     1024
#define HEADS   16
#define DH      64
#define MTOT    (BATCH*SEQ)
#define NEG_BIG 1e10f

// ---------------------------------------------------------------------------
// helpers
// ---------------------------------------------------------------------------
__device__ __forceinline__ float to_tf32(float x) {
    float r; asm("cvt.rna.tf32.f32 %0, %1;" : "=f"(r) : "f"(x)); return r;
}
__device__ __forceinline__ float4 cvt4(float4 v) {
    v.x = to_tf32(v.x); v.y = to_tf32(v.y); v.z = to_tf32(v.z); v.w = to_tf32(v.w);
    return v;
}
__device__ __forceinline__ u32 su32(const void* p) {
    return (u32)__cvta_generic_to_shared(p);
}
__device__ __forceinline__ void ldsm4(u32 &r0, u32 &r1, u32 &r2, u32 &r3, u32 addr) {
    asm volatile("ldmatrix.sync.aligned.m8n8.x4.shared.b16 {%0,%1,%2,%3}, [%4];"
        : "=r"(r0), "=r"(r1), "=r"(r2), "=r"(r3) : "r"(addr));
}
__device__ __forceinline__ void mma_tf32(float &c0, float &c1, float &c2, float &c3,
                                         u32 a0, u32 a1, u32 a2, u32 a3,
                                         u32 b0, u32 b1) {
    asm volatile("mma.sync.aligned.m16n8k8.row.col.f32.tf32.tf32.f32 "
                 "{%0,%1,%2,%3}, {%4,%5,%6,%7}, {%8,%9}, {%0,%1,%2,%3};"
        : "+f"(c0), "+f"(c1), "+f"(c2), "+f"(c3)
        : "r"(a0), "r"(a1), "r"(a2), "r"(a3), "r"(b0), "r"(b1));
}

// ---------------------------------------------------------------------------
// Scratch: projected Q/K/V (tf32-rounded fp32 bits), [B*S, 1024] row-major.
// ---------------------------------------------------------------------------
__device__ float g_qw[(size_t)MTOT * DIM];
__device__ float g_kw[(size_t)MTOT * DIM];
__device__ float g_vw[(size_t)MTOT * DIM];

// ---------------------------------------------------------------------------
// Projection GEMM: C[8192,1024] = tf32(A) @ tf32(W), fp32 accum.
// Block 128x128, BK=32, 256 thr = 8 warps in 4(m) x 2(n); warp tile 32x64.
// As[m][k] swizzled; Ws[n][k] (W transposed) swizzled.
// ---------------------------------------------------------------------------
__global__ __launch_bounds__(256) void proj_kernel(
    const float* __restrict__ A,
    const float* __restrict__ W,
    float* __restrict__ C)
{
    __shared__ float As[128 * 32];
    __shared__ float Ws[128 * 32];

    const int tid  = threadIdx.x;
    const int lane = tid & 31;
    const int warp = tid >> 5;
    const int wm = warp >> 1;            // 0..3
    const int wn = warp & 1;             // 0..1
    const int row0 = blockIdx.y * 128;
    const int col0 = blockIdx.x * 128;

    float acc[2][8][4];
    #pragma unroll
    for (int i = 0; i < 2; i++)
        #pragma unroll
        for (int j = 0; j < 8; j++)
            #pragma unroll
            for (int r = 0; r < 4; r++) acc[i][j][r] = 0.f;

    for (int kt = 0; kt < DIM; kt += 32) {
        // A tile: 128x32, float4 loads, swizzled STS.128
        #pragma unroll
        for (int p = 0; p < 4; p++) {
            int idx = tid + p * 256;
            int m  = idx >> 3;
            int c4 = idx & 7;
            float4 v = cvt4(*(const float4*)&A[(size_t)(row0 + m) * DIM + kt + 4 * c4]);
            int pc = c4 ^ (m & 7);
            *(float4*)&As[m * 32 + 4 * pc] = v;
        }
        // W tile: 32x128 -> Ws[n][k] transposed, scalar stores
        #pragma unroll
        for (int p = 0; p < 4; p++) {
            int idx = tid + p * 256;
            int k  = idx >> 5;
            int n4 = idx & 31;
            float4 v = cvt4(*(const float4*)&W[(size_t)(kt + k) * DIM + col0 + 4 * n4]);
            float vv[4] = {v.x, v.y, v.z, v.w};
            #pragma unroll
            for (int j = 0; j < 4; j++) {
                int n = 4 * n4 + j;
                int pc = (k >> 2) ^ (n & 7) ^ ((n >> 3) & 7);
                Ws[n * 32 + 4 * pc + (k & 3)] = vv[j];
            }
        }
        __syncthreads();

        #pragma unroll
        for (int ks = 0; ks < 4; ks++) {
            int chunk = 2 * ks + (lane >> 4);
            int rsel  = (lane & 7) + ((lane >> 3) & 1) * 8;
            // A fragments (2 m-frags)
            u32 a[2][4];
            #pragma unroll
            for (int mf = 0; mf < 2; mf++) {
                int row = wm * 32 + mf * 16 + rsel;
                int pc = chunk ^ (row & 7);
                ldsm4(a[mf][0], a[mf][1], a[mf][2], a[mf][3],
                      su32(&As[row * 32 + 4 * pc]));
            }
            // B fragments (8 n-frags via 4 x4-ldmatrix)
            u32 b[8][2];
            #pragma unroll
            for (int nfp = 0; nfp < 4; nfp++) {
                int row = wn * 64 + nfp * 16 + rsel;
                int pc = chunk ^ (row & 7) ^ ((row >> 3) & 7);
                u32 r0, r1, r2, r3;
                ldsm4(r0, r1, r2, r3, su32(&Ws[row * 32 + 4 * pc]));
                b[2 * nfp][0] = r0; b[2 * nfp][1] = r2;
                b[2 * nfp + 1][0] = r1; b[2 * nfp + 1][1] = r3;
            }
            #pragma unroll
            for (int mf = 0; mf < 2; mf++)
                #pragma unroll
                for (int nf = 0; nf < 8; nf++)
                    mma_tf32(acc[mf][nf][0], acc[mf][nf][1], acc[mf][nf][2], acc[mf][nf][3],
                             a[mf][0], a[mf][1], a[mf][2], a[mf][3],
                             b[nf][0], b[nf][1]);
        }
        __syncthreads();
    }

    // Epilogue: store tf32-rounded (consumed only by MMA downstream)
    const int g = lane >> 2;
    const int tg = lane & 3;
    #pragma unroll
    for (int mf = 0; mf < 2; mf++) {
        int r = row0 + wm * 32 + mf * 16 + g;
        #pragma unroll
        for (int nf = 0; nf < 8; nf++) {
            int c = col0 + wn * 64 + 8 * nf + 2 * tg;
            *(float2*)&C[(size_t)r * DIM + c] =
                make_float2(to_tf32(acc[mf][nf][0]), to_tf32(acc[mf][nf][1]));
            *(float2*)&C[(size_t)(r + 8) * DIM + c] =
                make_float2(to_tf32(acc[mf][nf][2]), to_tf32(acc[mf][nf][3]));
        }
    }
}

// ---------------------------------------------------------------------------
// Flash attention, tf32 mma. 128 threads = 4 warps; BQ=64 (16 q-rows/warp),
// BKV=64, DH=64. Q fragments register-resident; P reuses the Q smem region.
// smem: QP[64*64] | Ks[64*64] | Vt[64*64] | mask[64]
// ---------------------------------------------------------------------------
#define AQP_OFF 0
#define AKS_OFF (64*64)
#define AVT_OFF (2*64*64)
#define AMK_OFF (3*64*64)
#define A_SMEM_FLOATS (3*64*64 + 64)

__global__ __launch_bounds__(128) void attn_kernel(
    const float* __restrict__ qw,
    const float* __restrict__ kw,
    const float* __restrict__ vw,
    const float* __restrict__ v_mask,
    const float* __restrict__ q_mask,
    float* __restrict__ out)
{
    extern __shared__ float smem[];
    float* QP = smem + AQP_OFF;
    float* Ks = smem + AKS_OFF;
    float* Vt = smem + AVT_OFF;
    float* maskS = smem + AMK_OFF;

    const int tid  = threadIdx.x;
    const int lane = tid & 31;
    const int warp = tid >> 5;
    const int g  = lane >> 2;
    const int tg = lane & 3;
    const int q0 = blockIdx.x * 64;
    const int bh = blockIdx.y;
    const int b = bh / HEADS;
    const int h = bh % HEADS;

    const float* qbase = qw + (size_t)(b * SEQ + q0) * DIM + h * DH;

    // ---- Load Q tile (x 1/8, exact in tf32) into smem, swizzled ----
    #pragma unroll
    for (int p = 0; p < 8; p++) {
        int idx = tid + p * 128;
        int r  = idx >> 4;
        int c4 = idx & 15;
        float4 v = *(const float4*)&qbase[(size_t)r * DIM + 4 * c4];
        v.x *= 0.125f; v.y *= 0.125f; v.z *= 0.125f; v.w *= 0.125f;
        int pc = c4 ^ (r & 7);
        *(float4*)&QP[r * 64 + 4 * pc] = v;
    }
    __syncthreads();

    // ---- Q fragments: 8 k-steps, register resident ----
    const int rsel = (lane & 7) + ((lane >> 3) & 1) * 8;
    u32 qa[8][4];
    #pragma unroll
    for (int ks = 0; ks < 8; ks++) {
        int row = warp * 16 + rsel;
        int chunk = 2 * ks + (lane >> 4);
        int pc = chunk ^ (row & 7);
        ldsm4(qa[ks][0], qa[ks][1], qa[ks][2], qa[ks][3],
              su32(&QP[row * 64 + 4 * pc]));
    }
    __syncthreads();   // QP free for P reuse

    float o[8][4];
    float m_i[2] = {-1e30f, -1e30f};
    float l_i[2] = {0.f, 0.f};
    #pragma unroll
    for (int nf = 0; nf < 8; nf++)
        #pragma unroll
        for (int r = 0; r < 4; r++) o[nf][r] = 0.f;

    for (int kt = 0; kt < SEQ / 64; kt++) {
        const int c0 = kt * 64;
        const float* kbase = kw + (size_t)(b * SEQ + c0) * DIM + h * DH;
        const float* vbase = vw + (size_t)(b * SEQ + c0) * DIM + h * DH;

        __syncthreads();   // prev iteration consumers done

        // K tile natural [c][d], swizzled
        #pragma unroll
        for (int p = 0; p < 8; p++) {
            int idx = tid + p * 128;
            int r  = idx >> 4;
            int c4 = idx & 15;
            float4 v = *(const float4*)&kbase[(size_t)r * DIM + 4 * c4];
            int pc = c4 ^ (r & 7);
            *(float4*)&Ks[r * 64 + 4 * pc] = v;
        }
        // V tile transposed -> Vt[d][c], swizzled
        #pragma unroll
        for (int p = 0; p < 8; p++) {
            int idx = tid + p * 128;
            int c  = idx >> 4;
            int d4 = idx & 15;
            float4 v = *(const float4*)&vbase[(size_t)c * DIM + 4 * d4];
            float vv[4] = {v.x, v.y, v.z, v.w};
            #pragma unroll
            for (int j = 0; j < 4; j++) {
                int row = 4 * d4 + j;
                int pc = (c >> 2) ^ (row & 7) ^ ((row >> 3) & 7);
                Vt[row * 64 + 4 * pc + (c & 3)] = vv[j];
            }
        }
        if (tid < 64) maskS[tid] = v_mask[b * SEQ + c0 + tid];
        __syncthreads();

        // ---- S = Q K^T ----
        float s[8][4];
        #pragma unroll
        for (int nf = 0; nf < 8; nf++)
            #pragma unroll
            for (int r = 0; r < 4; r++) s[nf][r] = 0.f;

        #pragma unroll
        for (int ks = 0; ks < 8; ks++) {
            int chunk = 2 * ks + (lane >> 4);
            u32 kb[8][2];
            #pragma unroll
            for (int nfp = 0; nfp < 4; nfp++) {
                int row = nfp * 16 + rsel;
                int pc = chunk ^ (row & 7);
                u32 r0, r1, r2, r3;
                ldsm4(r0, r1, r2, r3, su32(&Ks[row * 64 + 4 * pc]));
                kb[2 * nfp][0] = r0; kb[2 * nfp][1] = r2;
                kb[2 * nfp + 1][0] = r1; kb[2 * nfp + 1][1] = r3;
            }
            #pragma unroll
            for (int nf = 0; nf < 8; nf++)
                mma_tf32(s[nf][0], s[nf][1], s[nf][2], s[nf][3],
                         qa[ks][0], qa[ks][1], qa[ks][2], qa[ks][3],
                         kb[nf][0], kb[nf][1]);
        }

        // ---- additive key mask ----
        #pragma unroll
        for (int nf = 0; nf < 8; nf++) {
            int col = 8 * nf + 2 * tg;
            float m0 = (1.0f - maskS[col])     * NEG_BIG;
            float m1 = (1.0f - maskS[col + 1]) * NEG_BIG;
            s[nf][0] -= m0; s[nf][1] -= m1;
            s[nf][2] -= m0; s[nf][3] -= m1;
        }

        // ---- online softmax ----
        float rmax0 = -1e30f, rmax1 = -1e30f;
        #pragma unroll
        for (int nf = 0; nf < 8; nf++) {
            rmax0 = fmaxf(rmax0, fmaxf(s[nf][0], s[nf][1]));
            rmax1 = fmaxf(rmax1, fmaxf(s[nf][2], s[nf][3]));
        }
        #pragma unroll
        for (int off = 1; off <= 2; off <<= 1) {
            rmax0 = fmaxf(rmax0, __shfl_xor_sync(0xffffffffu, rmax0, off));
            rmax1 = fmaxf(rmax1, __shfl_xor_sync(0xffffffffu, rmax1, off));
        }
        float mn0 = fmaxf(m_i[0], rmax0);
        float mn1 = fmaxf(m_i[1], rmax1);
        float fi0 = __expf(m_i[0] - mn0);
        float fi1 = __expf(m_i[1] - mn1);
        m_i[0] = mn0; m_i[1] = mn1;
        l_i[0] *= fi0; l_i[1] *= fi1;
        #pragma unroll
        for (int nf = 0; nf < 8; nf++) {
            o[nf][0] *= fi0; o[nf][1] *= fi0;
            o[nf][2] *= fi1; o[nf][3] *= fi1;
        }

        float ls0 = 0.f, ls1 = 0.f;
        #pragma unroll
        for (int nf = 0; nf < 8; nf++) {
            s[nf][0] = __expf(s[nf][0] - mn0);
            s[nf][1] = __expf(s[nf][1] - mn0);
            s[nf][2] = __expf(s[nf][2] - mn1);
            s[nf][3] = __expf(s[nf][3] - mn1);
            ls0 += s[nf][0] + s[nf][1];
            ls1 += s[nf][2] + s[nf][3];
        }
        #pragma unroll
        for (int off = 1; off <= 2; off <<= 1) {
            ls0 += __shfl_xor_sync(0xffffffffu, ls0, off);
            ls1 += __shfl_xor_sync(0xffffffffu, ls1, off);
        }
        l_i[0] += ls0; l_i[1] += ls1;

        // ---- P -> smem (tf32-rounded), per-warp private rows ----
        #pragma unroll
        for (int nf = 0; nf < 8; nf++) {
            int col = 8 * nf + 2 * tg;
            int chunk = col >> 2;
            int row = warp * 16 + g;
            int pc0 = chunk ^ (row & 7);
            *(float2*)&QP[row * 64 + 4 * pc0 + (col & 3)] =
                make_float2(to_tf32(s[nf][0]), to_tf32(s[nf][1]));
            int row2 = row + 8;
            int pc2 = chunk ^ (row2 & 7);
            *(float2*)&QP[row2 * 64 + 4 * pc2 + (col & 3)] =
                make_float2(to_tf32(s[nf][2]), to_tf32(s[nf][3]));
        }
        __syncwarp();

        // ---- O += P @ V ----
        #pragma unroll
        for (int ks = 0; ks < 8; ks++) {
            int chunk = 2 * ks + (lane >> 4);
            int prow = warp * 16 + rsel;
            int ppc = chunk ^ (prow & 7);
            u32 pa0, pa1, pa2, pa3;
            ldsm4(pa0, pa1, pa2, pa3, su32(&QP[prow * 64 + 4 * ppc]));

            u32 vb[8][2];
            #pragma unroll
            for (int nfp = 0; nfp < 4; nfp++) {
                int row = nfp * 16 + rsel;
                int pc = chunk ^ (row & 7) ^ ((row >> 3) & 7);
                u32 r0, r1, r2, r3;
                ldsm4(r0, r1, r2, r3, su32(&Vt[row * 64 + 4 * pc]));
                vb[2 * nfp][0] = r0; vb[2 * nfp][1] = r2;
                vb[2 * nfp + 1][0] = r1; vb[2 * nfp + 1][1] = r3;
            }
            #pragma unroll
            for (int nf = 0; nf < 8; nf++)
                mma_tf32(o[nf][0], o[nf][1], o[nf][2], o[nf][3],
                         pa0, pa1, pa2, pa3, vb[nf][0], vb[nf][1]);
        }
    }

    // ---- epilogue ----
    int r0g = q0 + warp * 16 + g;
    int r1g = r0g + 8;
    float inv0 = (l_i[0] > 0.f) ? 1.0f / l_i[0] : 0.f;
    float inv1 = (l_i[1] > 0.f) ? 1.0f / l_i[1] : 0.f;
    float qm0 = q_mask[b * SEQ + r0g] * inv0;
    float qm1 = q_mask[b * SEQ + r1g] * inv1;
    #pragma unroll
    for (int nf = 0; nf < 8; nf++) {
        int c = h * DH + 8 * nf + 2 * tg;
        *(float2*)&out[(size_t)(b * SEQ + r0g) * DIM + c] =
            make_float2(o[nf][0] * qm0, o[nf][1] * qm0);
        *(float2*)&out[(size_t)(b * SEQ + r1g) * DIM + c] =
            make_float2(o[nf][2] * qm1, o[nf][3] * qm1);
    }
}

// ---------------------------------------------------------------------------
// Launch
// ---------------------------------------------------------------------------
extern "C" void kernel_launch(void* const* d_in, const int* in_sizes, int n_in,
                              void* d_out, int out_size)
{
    const float* q_value = (const float*)d_in[0];
    const float* k_value = (const float*)d_in[1];
    const float* v_value = (const float*)d_in[2];
    const float* v_mask  = (const float*)d_in[3];
    const float* q_mask  = (const float*)d_in[4];
    const float* Wq      = (const float*)d_in[5];
    const float* Wk      = (const float*)d_in[6];
    const float* Wv      = (const float*)d_in[7];
    float* out = (float*)d_out;

    float *qw, *kw, *vw;
    cudaGetSymbolAddress((void**)&qw, g_qw);
    cudaGetSymbolAddress((void**)&kw, g_kw);
    cudaGetSymbolAddress((void**)&vw, g_vw);

    dim3 pGrid(DIM / 128, MTOT / 128);   // (8, 64)
    proj_kernel<<<pGrid, 256>>>(q_value, Wq, qw);
    proj_kernel<<<pGrid, 256>>>(k_value, Wk, kw);
    proj_kernel<<<pGrid, 256>>>(v_value, Wv, vw);

    const int smem_bytes = A_SMEM_FLOATS * (int)sizeof(float);   // 49408
    cudaFuncSetAttribute(attn_kernel,
                         cudaFuncAttributeMaxDynamicSharedMemorySize, smem_bytes);
    dim3 aGrid(SEQ / 64, BATCH * HEADS);   // (32, 64)
    attn_kernel<<<aGrid, 128, smem_bytes>>>(qw, kw, vw, v_mask, q_mask, out);
}

// round 9
// speedup vs baseline: 3.8060x; 1.3490x over previous
#include <cuda_runtime.h>
#include <cstdint>

typedef unsigned int u32;

#define BATCH   4
#define SEQ     2048
#define DIM     1024
#define HEADS   16
#define DH      64
#define MTOT    (BATCH*SEQ)
#define LOG2E      1.4426950408889634f
#define NEGBIG_L2  1.4426950408889634e10f
#define QSCL       (0.125f * LOG2E)

// ---------------------------------------------------------------------------
// helpers
// ---------------------------------------------------------------------------
__device__ __forceinline__ float to_tf32(float x) {
    float r; asm("cvt.rna.tf32.f32 %0, %1;" : "=f"(r) : "f"(x)); return r;
}
__device__ __forceinline__ float ex2(float x) {
    float r; asm("ex2.approx.ftz.f32 %0, %1;" : "=f"(r) : "f"(x)); return r;
}
__device__ __forceinline__ u32 su32(const void* p) {
    return (u32)__cvta_generic_to_shared(p);
}
__device__ __forceinline__ void ldsm4(u32 &r0, u32 &r1, u32 &r2, u32 &r3, u32 addr) {
    asm volatile("ldmatrix.sync.aligned.m8n8.x4.shared.b16 {%0,%1,%2,%3}, [%4];"
        : "=r"(r0), "=r"(r1), "=r"(r2), "=r"(r3) : "r"(addr));
}
__device__ __forceinline__ void mma_tf32(float &c0, float &c1, float &c2, float &c3,
                                         u32 a0, u32 a1, u32 a2, u32 a3,
                                         u32 b0, u32 b1) {
    asm volatile("mma.sync.aligned.m16n8k8.row.col.f32.tf32.tf32.f32 "
                 "{%0,%1,%2,%3}, {%4,%5,%6,%7}, {%8,%9}, {%0,%1,%2,%3};"
        : "+f"(c0), "+f"(c1), "+f"(c2), "+f"(c3)
        : "r"(a0), "r"(a1), "r"(a2), "r"(a3), "r"(b0), "r"(b1));
}
__device__ __forceinline__ void cpa16(u32 dst, const void* src) {
    asm volatile("cp.async.cg.shared.global [%0], [%1], 16;" :: "r"(dst), "l"(src));
}
__device__ __forceinline__ void cpa4(u32 dst, const void* src) {
    asm volatile("cp.async.ca.shared.global [%0], [%1], 4;" :: "r"(dst), "l"(src));
}
__device__ __forceinline__ void cp_commit() {
    asm volatile("cp.async.commit_group;" ::: "memory");
}
__device__ __forceinline__ void cp_wait0() {
    asm volatile("cp.async.wait_group 0;" ::: "memory");
}

// ---------------------------------------------------------------------------
// Scratch
// ---------------------------------------------------------------------------
__device__ float g_qw[(size_t)MTOT * DIM];     // Q proj, [b*S][h*dh], tf32
__device__ float g_kw[(size_t)MTOT * DIM];     // K proj, [b*S][h*dh], tf32
__device__ float g_vwt[(size_t)MTOT * DIM];    // V proj TRANSPOSED [b][h][d][s], tf32
__device__ float g_wqt[(size_t)DIM * DIM];     // W^T, tf32
__device__ float g_wkt[(size_t)DIM * DIM];
__device__ float g_wvt[(size_t)DIM * DIM];

// ---------------------------------------------------------------------------
// W transpose + tf32 round: Wt[n][k] = tf32(W[k][n])
// ---------------------------------------------------------------------------
__global__ void wtrans_kernel(const float* __restrict__ W, float* __restrict__ Wt) {
    __shared__ float t[32][33];
    int n0 = blockIdx.x * 32, k0 = blockIdx.y * 32;
    int tx = threadIdx.x, ty = threadIdx.y;
    #pragma unroll
    for (int i = 0; i < 4; i++)
        t[ty + 8 * i][tx] = to_tf32(W[(size_t)(k0 + ty + 8 * i) * DIM + n0 + tx]);
    __syncthreads();
    #pragma unroll
    for (int i = 0; i < 4; i++)
        Wt[(size_t)(n0 + ty + 8 * i) * DIM + k0 + tx] = t[tx][ty + 8 * i];
}

// ---------------------------------------------------------------------------
// Projection GEMM: C = tf32(A) @ Wt^T.  A [8192,1024]; Wt [n][k], pre-rounded.
// 128x128 tile, BK=32, 2-stage cp.async. 8 warps (4m x 2n), warp tile 32x64.
// vmode=1: store transposed into [b][h][d][s].
// ---------------------------------------------------------------------------
#define PSTR 36
#define PSTG (128 * PSTR)

__global__ __launch_bounds__(256) void proj_kernel(
    const float* __restrict__ A,
    const float* __restrict__ Wt,
    float* __restrict__ C,
    int vmode)
{
    extern __shared__ float ps[];
    float* As = ps;                 // 2 stages x 128 x PSTR
    float* Ws = ps + 2 * PSTG;

    const int tid  = threadIdx.x;
    const int lane = tid & 31;
    const int warp = tid >> 5;
    const int wm = warp >> 1;
    const int wn = warp & 1;
    const int row0 = blockIdx.y * 128;
    const int col0 = blockIdx.x * 128;
    const int rsel = (lane & 7) + ((lane >> 3) & 1) * 8;

    float acc[2][8][4];
    #pragma unroll
    for (int i = 0; i < 2; i++)
        #pragma unroll
        for (int j = 0; j < 8; j++)
            #pragma unroll
            for (int r = 0; r < 4; r++) acc[i][j][r] = 0.f;

    // stage issue
    {
        #pragma unroll
        for (int p = 0; p < 4; p++) {
            int idx = tid + p * 256;
            int r = idx >> 3, c4 = idx & 7;
            cpa16(su32(As + r * PSTR + 4 * c4), &A[(size_t)(row0 + r) * DIM + 4 * c4]);
            cpa16(su32(Ws + r * PSTR + 4 * c4), &Wt[(size_t)(col0 + r) * DIM + 4 * c4]);
        }
        cp_commit();
    }

    for (int t = 0; t < DIM / 32; t++) {
        int buf = t & 1;
        cp_wait0();
        __syncthreads();
        if (t < DIM / 32 - 1) {
            int kt = (t + 1) * 32;
            float* Ad = As + (buf ^ 1) * PSTG;
            float* Wd = Ws + (buf ^ 1) * PSTG;
            #pragma unroll
            for (int p = 0; p < 4; p++) {
                int idx = tid + p * 256;
                int r = idx >> 3, c4 = idx & 7;
                cpa16(su32(Ad + r * PSTR + 4 * c4), &A[(size_t)(row0 + r) * DIM + kt + 4 * c4]);
                cpa16(su32(Wd + r * PSTR + 4 * c4), &Wt[(size_t)(col0 + r) * DIM + kt + 4 * c4]);
            }
            cp_commit();
        }
        float* Ab = As + buf * PSTG;
        float* Wb = Ws + buf * PSTG;

        #pragma unroll
        for (int ks = 0; ks < 4; ks++) {
            int chunk = 2 * ks + (lane >> 4);
            u32 a[2][4];
            #pragma unroll
            for (int mf = 0; mf < 2; mf++) {
                int row = wm * 32 + mf * 16 + rsel;
                ldsm4(a[mf][0], a[mf][1], a[mf][2], a[mf][3],
                      su32(Ab + row * PSTR + 4 * chunk));
                #pragma unroll
                for (int j = 0; j < 4; j++)
                    a[mf][j] = __float_as_uint(to_tf32(__uint_as_float(a[mf][j])));
            }
            u32 b[8][2];
            #pragma unroll
            for (int nfp = 0; nfp < 4; nfp++) {
                int row = wn * 64 + nfp * 16 + rsel;
                u32 r0, r1, r2, r3;
                ldsm4(r0, r1, r2, r3, su32(Wb + row * PSTR + 4 * chunk));
                b[2 * nfp][0] = r0; b[2 * nfp][1] = r2;
                b[2 * nfp + 1][0] = r1; b[2 * nfp + 1][1] = r3;
            }
            #pragma unroll
            for (int mf = 0; mf < 2; mf++)
                #pragma unroll
                for (int nf = 0; nf < 8; nf++)
                    mma_tf32(acc[mf][nf][0], acc[mf][nf][1], acc[mf][nf][2], acc[mf][nf][3],
                             a[mf][0], a[mf][1], a[mf][2], a[mf][3],
                             b[nf][0], b[nf][1]);
        }
        __syncthreads();
    }

    const int g = lane >> 2;
    const int tg = lane & 3;
    if (!vmode) {
        #pragma unroll
        for (int mf = 0; mf < 2; mf++) {
            int r = row0 + wm * 32 + mf * 16 + g;
            #pragma unroll
            for (int nf = 0; nf < 8; nf++) {
                int c = col0 + wn * 64 + 8 * nf + 2 * tg;
                *(float2*)&C[(size_t)r * DIM + c] =
                    make_float2(to_tf32(acc[mf][nf][0]), to_tf32(acc[mf][nf][1]));
                *(float2*)&C[(size_t)(r + 8) * DIM + c] =
                    make_float2(to_tf32(acc[mf][nf][2]), to_tf32(acc[mf][nf][3]));
            }
        }
    } else {
        // transposed store: C[((b*H + h)*DH + d)*SEQ + s]
        #pragma unroll
        for (int mf = 0; mf < 2; mf++) {
            int r = row0 + wm * 32 + mf * 16 + g;
            int bb = r >> 11, s1 = r & (SEQ - 1);
            #pragma unroll
            for (int nf = 0; nf < 8; nf++) {
                int c = col0 + wn * 64 + 8 * nf + 2 * tg;
                int h = c >> 6, d = c & 63;
                size_t base = ((size_t)(bb * HEADS + h) * DH + d) * SEQ + s1;
                C[base]           = to_tf32(acc[mf][nf][0]);
                C[base + SEQ]     = to_tf32(acc[mf][nf][1]);
                C[base + 8]       = to_tf32(acc[mf][nf][2]);
                C[base + SEQ + 8] = to_tf32(acc[mf][nf][3]);
            }
        }
    }
}

// ---------------------------------------------------------------------------
// Flash attention: 128 thr / 4 warps. BQ=128 (32 q-rows per warp, 2 m-frags),
// BKV=64, DH=64, 2-stage cp.async for K and V^T. Q frags register-resident;
// P reuses the Q smem tile (warp-private rows).
// smem floats: QP[128*68] | K[2][64*68] | V[2][64*68] | mask[2][64]
// ---------------------------------------------------------------------------
#define ASTR 68
#define AK_OFF (128 * ASTR)                 // 8704
#define AV_OFF (AK_OFF + 2 * 64 * ASTR)     // 17408
#define AM_OFF (AV_OFF + 2 * 64 * ASTR)     // 26112
#define A_SMEM_FLOATS (AM_OFF + 2 * 64)     // 26240 -> 104960 B

__global__ __launch_bounds__(128) void attn_kernel(
    const float* __restrict__ qw,
    const float* __restrict__ kw,
    const float* __restrict__ vwt,
    const float* __restrict__ v_mask,
    const float* __restrict__ q_mask,
    float* __restrict__ out)
{
    extern __shared__ float smem[];
    float* QP  = smem;
    float* Ksm = smem + AK_OFF;
    float* Vsm = smem + AV_OFF;
    float* Msm = smem + AM_OFF;

    const int tid  = threadIdx.x;
    const int lane = tid & 31;
    const int warp = tid >> 5;
    const int g  = lane >> 2;
    const int tg = lane & 3;
    const int q0 = blockIdx.x * 128;
    const int bh = blockIdx.y;
    const int b = bh / HEADS;
    const int h = bh % HEADS;
    const int rsel = (lane & 7) + ((lane >> 3) & 1) * 8;

    const float* qbase  = qw  + (size_t)(b * SEQ + q0) * DIM + h * DH;
    const float* kbase0 = kw  + (size_t)(b * SEQ) * DIM + h * DH;
    const float* vtbase = vwt + (size_t)(b * HEADS + h) * DH * SEQ;

    // ---- Q tile -> smem (scaled by 0.125*log2e, rna-rounded to tf32) ----
    #pragma unroll
    for (int p = 0; p < 16; p++) {
        int idx = tid + p * 128;
        int r  = idx >> 4;
        int c4 = idx & 15;
        float4 v = *(const float4*)&qbase[(size_t)r * DIM + 4 * c4];
        v.x = to_tf32(v.x * QSCL); v.y = to_tf32(v.y * QSCL);
        v.z = to_tf32(v.z * QSCL); v.w = to_tf32(v.w * QSCL);
        *(float4*)&QP[r * ASTR + 4 * c4] = v;
    }
    __syncthreads();

    // ---- Q fragments: 2 m-frags x 8 k-steps, register resident ----
    u32 qa[2][8][4];
    #pragma unroll
    for (int mf = 0; mf < 2; mf++)
        #pragma unroll
        for (int ks = 0; ks < 8; ks++) {
            int row = warp * 32 + mf * 16 + rsel;
            int chunk = 2 * ks + (lane >> 4);
            ldsm4(qa[mf][ks][0], qa[mf][ks][1], qa[mf][ks][2], qa[mf][ks][3],
                  su32(&QP[row * ASTR + 4 * chunk]));
        }
    __syncthreads();   // QP free for P reuse

    float m_i[4] = {-1e30f, -1e30f, -1e30f, -1e30f};
    float l_i[4] = {0.f, 0.f, 0.f, 0.f};
    float o[2][8][4];
    #pragma unroll
    for (int mf = 0; mf < 2; mf++)
        #pragma unroll
        for (int nf = 0; nf < 8; nf++)
            #pragma unroll
            for (int r = 0; r < 4; r++) o[mf][nf][r] = 0.f;

    // stage-0 issue
    {
        #pragma unroll
        for (int p = 0; p < 8; p++) {
            int idx = tid + p * 128;
            int r = idx >> 4, c4 = idx & 15;
            cpa16(su32(Ksm + r * ASTR + 4 * c4), kbase0 + (size_t)r * DIM + 4 * c4);
            cpa16(su32(Vsm + r * ASTR + 4 * c4), vtbase + (size_t)r * SEQ + 4 * c4);
        }
        if (tid < 64) cpa4(su32(Msm + tid), v_mask + b * SEQ + tid);
        cp_commit();
    }

    for (int kt = 0; kt < SEQ / 64; kt++) {
        int buf = kt & 1;
        cp_wait0();
        __syncthreads();
        if (kt < SEQ / 64 - 1) {
            int c1 = (kt + 1) * 64;
            float* Kd = Ksm + (buf ^ 1) * 64 * ASTR;
            float* Vd = Vsm + (buf ^ 1) * 64 * ASTR;
            const float* kb = kbase0 + (size_t)c1 * DIM;
            #pragma unroll
            for (int p = 0; p < 8; p++) {
                int idx = tid + p * 128;
                int r = idx >> 4, c4 = idx & 15;
                cpa16(su32(Kd + r * ASTR + 4 * c4), kb + (size_t)r * DIM + 4 * c4);
                cpa16(su32(Vd + r * ASTR + 4 * c4), vtbase + (size_t)r * SEQ + c1 + 4 * c4);
            }
            if (tid < 64) cpa4(su32(Msm + (buf ^ 1) * 64 + tid), v_mask + b * SEQ + c1 + tid);
            cp_commit();
        }
        float* Kb = Ksm + buf * 64 * ASTR;
        float* Vb = Vsm + buf * 64 * ASTR;
        float* Mb = Msm + buf * 64;

        // ---- S = Q K^T (log2 domain) ----
        float s[2][8][4];
        #pragma unroll
        for (int mf = 0; mf < 2; mf++)
            #pragma unroll
            for (int nf = 0; nf < 8; nf++)
                #pragma unroll
                for (int r = 0; r < 4; r++) s[mf][nf][r] = 0.f;

        #pragma unroll
        for (int ks = 0; ks < 8; ks++) {
            int chunk = 2 * ks + (lane >> 4);
            u32 kb2[8][2];
            #pragma unroll
            for (int nfp = 0; nfp < 4; nfp++) {
                int row = nfp * 16 + rsel;
                u32 r0, r1, r2, r3;
                ldsm4(r0, r1, r2, r3, su32(Kb + row * ASTR + 4 * chunk));
                kb2[2 * nfp][0] = r0; kb2[2 * nfp][1] = r2;
                kb2[2 * nfp + 1][0] = r1; kb2[2 * nfp + 1][1] = r3;
            }
            #pragma unroll
            for (int mf = 0; mf < 2; mf++)
                #pragma unroll
                for (int nf = 0; nf < 8; nf++)
                    mma_tf32(s[mf][nf][0], s[mf][nf][1], s[mf][nf][2], s[mf][nf][3],
                             qa[mf][ks][0], qa[mf][ks][1], qa[mf][ks][2], qa[mf][ks][3],
                             kb2[nf][0], kb2[nf][1]);
        }

        // ---- additive key mask (log2 domain) ----
        #pragma unroll
        for (int nf = 0; nf < 8; nf++) {
            int col = 8 * nf + 2 * tg;
            float m0 = (1.0f - Mb[col])     * NEGBIG_L2;
            float m1 = (1.0f - Mb[col + 1]) * NEGBIG_L2;
            #pragma unroll
            for (int mf = 0; mf < 2; mf++) {
                s[mf][nf][0] -= m0; s[mf][nf][1] -= m1;
                s[mf][nf][2] -= m0; s[mf][nf][3] -= m1;
            }
        }

        // ---- online softmax (base-2) ----
        #pragma unroll
        for (int mf = 0; mf < 2; mf++) {
            float rmax0 = -1e30f, rmax1 = -1e30f;
            #pragma unroll
            for (int nf = 0; nf < 8; nf++) {
                rmax0 = fmaxf(rmax0, fmaxf(s[mf][nf][0], s[mf][nf][1]));
                rmax1 = fmaxf(rmax1, fmaxf(s[mf][nf][2], s[mf][nf][3]));
            }
            #pragma unroll
            for (int off = 1; off <= 2; off <<= 1) {
                rmax0 = fmaxf(rmax0, __shfl_xor_sync(0xffffffffu, rmax0, off));
                rmax1 = fmaxf(rmax1, __shfl_xor_sync(0xffffffffu, rmax1, off));
            }
            float mn0 = fmaxf(m_i[2 * mf],     rmax0);
            float mn1 = fmaxf(m_i[2 * mf + 1], rmax1);
            float fi0 = ex2(m_i[2 * mf]     - mn0);
            float fi1 = ex2(m_i[2 * mf + 1] - mn1);
            m_i[2 * mf] = mn0; m_i[2 * mf + 1] = mn1;
            l_i[2 * mf] *= fi0; l_i[2 * mf + 1] *= fi1;
            #pragma unroll
            for (int nf = 0; nf < 8; nf++) {
                o[mf][nf][0] *= fi0; o[mf][nf][1] *= fi0;
                o[mf][nf][2] *= fi1; o[mf][nf][3] *= fi1;
            }
            float ls0 = 0.f, ls1 = 0.f;
            #pragma unroll
            for (int nf = 0; nf < 8; nf++) {
                s[mf][nf][0] = ex2(s[mf][nf][0] - mn0);
                s[mf][nf][1] = ex2(s[mf][nf][1] - mn0);
                s[mf][nf][2] = ex2(s[mf][nf][2] - mn1);
                s[mf][nf][3] = ex2(s[mf][nf][3] - mn1);
                ls0 += s[mf][nf][0] + s[mf][nf][1];
                ls1 += s[mf][nf][2] + s[mf][nf][3];
            }
            #pragma unroll
            for (int off = 1; off <= 2; off <<= 1) {
                ls0 += __shfl_xor_sync(0xffffffffu, ls0, off);
                ls1 += __shfl_xor_sync(0xffffffffu, ls1, off);
            }
            l_i[2 * mf] += ls0; l_i[2 * mf + 1] += ls1;
        }

        // ---- P -> smem (tf32-rounded), warp-private rows ----
        #pragma unroll
        for (int mf = 0; mf < 2; mf++) {
            int row = warp * 32 + mf * 16 + g;
            #pragma unroll
            for (int nf = 0; nf < 8; nf++) {
                int col = 8 * nf + 2 * tg;
                *(float2*)&QP[row * ASTR + col] =
                    make_float2(to_tf32(s[mf][nf][0]), to_tf32(s[mf][nf][1]));
                *(float2*)&QP[(row + 8) * ASTR + col] =
                    make_float2(to_tf32(s[mf][nf][2]), to_tf32(s[mf][nf][3]));
            }
        }
        __syncwarp();

        // ---- O += P @ V^T ----
        #pragma unroll
        for (int ks = 0; ks < 8; ks++) {
            int chunk = 2 * ks + (lane >> 4);
            u32 pa[2][4];
            #pragma unroll
            for (int mf = 0; mf < 2; mf++) {
                int row = warp * 32 + mf * 16 + rsel;
                ldsm4(pa[mf][0], pa[mf][1], pa[mf][2], pa[mf][3],
                      su32(&QP[row * ASTR + 4 * chunk]));
            }
            u32 vb2[8][2];
            #pragma unroll
            for (int nfp = 0; nfp < 4; nfp++) {
                int row = nfp * 16 + rsel;
                u32 r0, r1, r2, r3;
                ldsm4(r0, r1, r2, r3, su32(Vb + row * ASTR + 4 * chunk));
                vb2[2 * nfp][0] = r0; vb2[2 * nfp][1] = r2;
                vb2[2 * nfp + 1][0] = r1; vb2[2 * nfp + 1][1] = r3;
            }
            #pragma unroll
            for (int mf = 0; mf < 2; mf++)
                #pragma unroll
                for (int nf = 0; nf < 8; nf++)
                    mma_tf32(o[mf][nf][0], o[mf][nf][1], o[mf][nf][2], o[mf][nf][3],
                             pa[mf][0], pa[mf][1], pa[mf][2], pa[mf][3],
                             vb2[nf][0], vb2[nf][1]);
        }
        __syncthreads();
    }

    // ---- epilogue ----
    #pragma unroll
    for (int mf = 0; mf < 2; mf++) {
        int r0g = q0 + warp * 32 + mf * 16 + g;
        int r1g = r0g + 8;
        float inv0 = (l_i[2 * mf]     > 0.f) ? 1.0f / l_i[2 * mf]     : 0.f;
        float inv1 = (l_i[2 * mf + 1] > 0.f) ? 1.0f / l_i[2 * mf + 1] : 0.f;
        float qm0 = q_mask[b * SEQ + r0g] * inv0;
        float qm1 = q_mask[b * SEQ + r1g] * inv1;
        #pragma unroll
        for (int nf = 0; nf < 8; nf++) {
            int c = h * DH + 8 * nf + 2 * tg;
            *(float2*)&out[(size_t)(b * SEQ + r0g) * DIM + c] =
                make_float2(o[mf][nf][0] * qm0, o[mf][nf][1] * qm0);
            *(float2*)&out[(size_t)(b * SEQ + r1g) * DIM + c] =
                make_float2(o[mf][nf][2] * qm1, o[mf][nf][3] * qm1);
        }
    }
}

// ---------------------------------------------------------------------------
// Launch
// ---------------------------------------------------------------------------
extern "C" void kernel_launch(void* const* d_in, const int* in_sizes, int n_in,
                              void* d_out, int out_size)
{
    const float* q_value = (const float*)d_in[0];
    const float* k_value = (const float*)d_in[1];
    const float* v_value = (const float*)d_in[2];
    const float* v_mask  = (const float*)d_in[3];
    const float* q_mask  = (const float*)d_in[4];
    const float* Wq      = (const float*)d_in[5];
    const float* Wk      = (const float*)d_in[6];
    const float* Wv      = (const float*)d_in[7];
    float* out = (float*)d_out;

    float *qw, *kw, *vwt, *wqt, *wkt, *wvt;
    cudaGetSymbolAddress((void**)&qw,  g_qw);
    cudaGetSymbolAddress((void**)&kw,  g_kw);
    cudaGetSymbolAddress((void**)&vwt, g_vwt);
    cudaGetSymbolAddress((void**)&wqt, g_wqt);
    cudaGetSymbolAddress((void**)&wkt, g_wkt);
    cudaGetSymbolAddress((void**)&wvt, g_wvt);

    dim3 wtG(DIM / 32, DIM / 32), wtB(32, 8);
    wtrans_kernel<<<wtG, wtB>>>(Wq, wqt);
    wtrans_kernel<<<wtG, wtB>>>(Wk, wkt);
    wtrans_kernel<<<wtG, wtB>>>(Wv, wvt);

    const int proj_smem = 4 * PSTG * (int)sizeof(float);   // 73728
    cudaFuncSetAttribute(proj_kernel,
                         cudaFuncAttributeMaxDynamicSharedMemorySize, proj_smem);
    dim3 pGrid(DIM / 128, MTOT / 128);   // (8, 64)
    proj_kernel<<<pGrid, 256, proj_smem>>>(q_value, wqt, qw, 0);
    proj_kernel<<<pGrid, 256, proj_smem>>>(k_value, wkt, kw, 0);
    proj_kernel<<<pGrid, 256, proj_smem>>>(v_value, wvt, vwt, 1);

    const int attn_smem = A_SMEM_FLOATS * (int)sizeof(float);   // 104960
    cudaFuncSetAttribute(attn_kernel,
                         cudaFuncAttributeMaxDynamicSharedMemorySize, attn_smem);
    dim3 aGrid(SEQ / 128, BATCH * HEADS);   // (16, 64)
    attn_kernel<<<aGrid, 128, attn_smem>>>(qw, kw, vwt, v_mask, q_mask, out);
}